// round 9
// baseline (speedup 1.0000x reference)
#include <cuda_runtime.h>
#include <cuda_fp16.h>
#include <cstdint>

// Problem constants (fixed by the dataset's setup_inputs)
#define HH   12
#define LL   512
#define QKVN 2304       // 3*768
#define NNZZ 2048       // B*L
#define BHH  48         // B*H

// Scratch (allocation-free rule: __device__ global)
__device__ __half g_qkvh[(size_t)NNZZ * QKVN];   // QKV output, fp16

// ---------------------------------------------------------------------------
// helpers
// ---------------------------------------------------------------------------
__device__ __forceinline__ uint32_t smem_u32(const void* p) {
    uint32_t a;
    asm("{ .reg .u64 t; cvta.to.shared.u64 t, %1; cvt.u32.u64 %0, t; }"
        : "=r"(a) : "l"(p));
    return a;
}
__device__ __forceinline__ void mma_f16(float* c, const uint32_t* a, const uint32_t* b) {
    asm volatile(
        "mma.sync.aligned.m16n8k16.row.col.f32.f16.f16.f32 "
        "{%0,%1,%2,%3},{%4,%5,%6,%7},{%8,%9},{%0,%1,%2,%3};"
        : "+f"(c[0]), "+f"(c[1]), "+f"(c[2]), "+f"(c[3])
        : "r"(a[0]), "r"(a[1]), "r"(a[2]), "r"(a[3]), "r"(b[0]), "r"(b[1]));
}
__device__ __forceinline__ void ldm_x4(uint32_t* r, uint32_t addr) {
    asm volatile("ldmatrix.sync.aligned.m8n8.x4.shared.b16 {%0,%1,%2,%3}, [%4];"
                 : "=r"(r[0]), "=r"(r[1]), "=r"(r[2]), "=r"(r[3]) : "r"(addr));
}
__device__ __forceinline__ void ldm_x4t(uint32_t* r, uint32_t addr) {
    asm volatile("ldmatrix.sync.aligned.m8n8.x4.trans.shared.b16 {%0,%1,%2,%3}, [%4];"
                 : "=r"(r[0]), "=r"(r[1]), "=r"(r[2]), "=r"(r[3]) : "r"(addr));
}
__device__ __forceinline__ void cp16(uint32_t dst, const void* src) {
    asm volatile("cp.async.cg.shared.global [%0], [%1], 16;" :: "r"(dst), "l"(src));
}
__device__ __forceinline__ void cp_commit() { asm volatile("cp.async.commit_group;"); }
__device__ __forceinline__ void cp_wait1()  { asm volatile("cp.async.wait_group 1;"); }
__device__ __forceinline__ void cp_wait0()  { asm volatile("cp.async.wait_group 0;"); }

// pack 16 fp32 (4 float4) into 16 fp16 (2 uint4)
__device__ __forceinline__ void pack16(const float4* r, uint4* u) {
#pragma unroll
    for (int q = 0; q < 2; q++) {
        __half2 h0 = __floats2half2_rn(r[q * 2].x,     r[q * 2].y);
        __half2 h1 = __floats2half2_rn(r[q * 2].z,     r[q * 2].w);
        __half2 h2 = __floats2half2_rn(r[q * 2 + 1].x, r[q * 2 + 1].y);
        __half2 h3 = __floats2half2_rn(r[q * 2 + 1].z, r[q * 2 + 1].w);
        u[q].x = *reinterpret_cast<uint32_t*>(&h0);
        u[q].y = *reinterpret_cast<uint32_t*>(&h1);
        u[q].z = *reinterpret_cast<uint32_t*>(&h2);
        u[q].w = *reinterpret_cast<uint32_t*>(&h3);
    }
}

// ---------------------------------------------------------------------------
// Kernel A: QKV = X @ W^T + b, fp32->fp16 conversion FUSED (register-staged).
// Block 128(M) x 128(N), 8 warps (2x4), warp 64x32, ktile=32 halves.
// Each thread LDGs fp32 two ktiles ahead (2 alternating reg sets), converts
// and STS's fp16 one ktile ahead into a 3-stage smem ring for ldmatrix.
// ---------------------------------------------------------------------------
__global__ void __launch_bounds__(256) qkv_h(const float* __restrict__ X,
                                             const float* __restrict__ W,
                                             const float* __restrict__ Wb) {
    __shared__ __align__(16) __half sA[3][128 * 40];
    __shared__ __align__(16) __half sB[3][128 * 40];
    __shared__ float sWb[128];

    const int t    = threadIdx.x;
    const int w    = t >> 5, lane = t & 31;
    const int g    = lane >> 2, t3 = lane & 3;
    const int wm   = (w >> 2) * 64;
    const int wn   = (w & 3) * 32;
    const int m0   = blockIdx.y * 128;
    const int n0   = blockIdx.x * 128;

    if (t < 128) sWb[t] = Wb[n0 + t];

    float c[4][4][4];
#pragma unroll
    for (int mf = 0; mf < 4; mf++)
#pragma unroll
        for (int nf = 0; nf < 4; nf++)
#pragma unroll
            for (int r = 0; r < 4; r++) c[mf][nf][r] = 0.f;

    const uint32_t aB = smem_u32(&sA[0][0]);
    const uint32_t bB = smem_u32(&sB[0][0]);

    const int arow = lane & 15;
    const int acol = (lane >> 4) * 16;
    const int brow = (lane & 7) + ((lane >> 4) & 1) * 8;
    const int bcol = ((lane >> 3) & 1) * 16;

    // load/convert assignment: thread -> (row, 16-elem column half)
    const int lrow = t >> 1;
    const int lcb  = (t & 1) * 16;
    const float* xp = X + (size_t)(m0 + lrow) * 768 + lcb;
    const float* wp = W + (size_t)(n0 + lrow) * 768 + lcb;
    const uint32_t stsOff = (uint32_t)(lrow * 80 + lcb * 2);

    float4 rAx[4], rBx[4];   // even-kt register set
    float4 rAy[4], rBy[4];   // odd-kt register set

    auto ldg_set = [&](float4* ra, float4* rb, int kt) {
        const float* xq = xp + kt * 32;
        const float* wq = wp + kt * 32;
#pragma unroll
        for (int j = 0; j < 4; j++) {
            ra[j] = *(const float4*)(xq + 4 * j);
            rb[j] = *(const float4*)(wq + 4 * j);
        }
    };
    auto sts_set = [&](const float4* ra, const float4* rb, int st) {
        uint4 ua[2], ub[2];
        pack16(ra, ua);
        pack16(rb, ub);
        *(uint4*)((char*)&sA[st][0] + stsOff)      = ua[0];
        *(uint4*)((char*)&sA[st][0] + stsOff + 16) = ua[1];
        *(uint4*)((char*)&sB[st][0] + stsOff)      = ub[0];
        *(uint4*)((char*)&sB[st][0] + stsOff + 16) = ub[1];
    };

    // prologue: fill stages 0,1; prefetch kt=2,3 into regs
    ldg_set(rAx, rBx, 0);
    ldg_set(rAy, rBy, 1);
    sts_set(rAx, rBx, 0);
    ldg_set(rAx, rBx, 2);
    sts_set(rAy, rBy, 1);
    ldg_set(rAy, rBy, 3);
    __syncthreads();

    for (int kt = 0; kt < 24; kt++) {
        const int st = kt % 3;

        // compute on stage st
#pragma unroll
        for (int ks = 0; ks < 2; ks++) {
            uint32_t a[4][4], bk[2][4];
#pragma unroll
            for (int mf = 0; mf < 4; mf++)
                ldm_x4(a[mf], aB + (uint32_t)(st * 10240 +
                       (wm + mf * 16 + arow) * 80 + acol + ks * 32));
#pragma unroll
            for (int nf2 = 0; nf2 < 2; nf2++)
                ldm_x4(bk[nf2], bB + (uint32_t)(st * 10240 +
                       (wn + nf2 * 16 + brow) * 80 + bcol + ks * 32));
#pragma unroll
            for (int mf = 0; mf < 4; mf++)
#pragma unroll
                for (int nf = 0; nf < 4; nf++) {
                    uint32_t bb[2] = { bk[nf >> 1][(nf & 1) * 2],
                                       bk[nf >> 1][(nf & 1) * 2 + 1] };
                    mma_f16(c[mf][nf], a[mf], bb);
                }
        }

        // stage (kt+2): convert regs -> smem; refill regs with (kt+4)
        if (kt + 2 < 24) {
            const int st2 = (kt + 2) % 3;
            if ((kt & 1) == 0) {
                sts_set(rAx, rBx, st2);
                if (kt + 4 < 24) ldg_set(rAx, rBx, kt + 4);
            } else {
                sts_set(rAy, rBy, st2);
                if (kt + 4 < 24) ldg_set(rAy, rBy, kt + 4);
            }
        }
        __syncthreads();
    }

#pragma unroll
    for (int mf = 0; mf < 4; mf++) {
        const int r0 = m0 + wm + mf * 16 + g;
#pragma unroll
        for (int nf = 0; nf < 4; nf++) {
            const int col = n0 + wn + nf * 8 + 2 * t3;
            const float b0 = sWb[col - n0], b1 = sWb[col - n0 + 1];
            __half2 h0 = __floats2half2_rn(c[mf][nf][0] + b0, c[mf][nf][1] + b1);
            __half2 h1 = __floats2half2_rn(c[mf][nf][2] + b0, c[mf][nf][3] + b1);
            *(__half2*)&g_qkvh[(size_t)r0 * QKVN + col]       = h0;
            *(__half2*)&g_qkvh[(size_t)(r0 + 8) * QKVN + col] = h1;
        }
    }
}

// ---------------------------------------------------------------------------
// Kernel B: fused attention (unchanged from R8): fp16 mma, fp32 accum,
// one-pass softmax, 16 kv-chunks of 32, 3-stage cp.async (V 4-stage),
// software-pipelined S(k) ; PV(k-1) ; exp(k). 3 CTAs/SM, fully resident.
// ---------------------------------------------------------------------------
__global__ void __launch_bounds__(128, 3) attn_h(const float* __restrict__ bias,
                                                 float* __restrict__ out) {
    __shared__ __align__(16) __half Qs[64][72];
    __shared__ __align__(16) __half Ks[3][32][72];
    __shared__ __align__(16) __half Vs[4][32][72];
    __shared__ __align__(16) __half Ps[64][40];
    __shared__ __align__(16) float  Bs[3][64][36];
    __shared__ float rs[64];

    const int t  = threadIdx.x;
    const int w  = t >> 5, lane = t & 31;
    const int g  = lane >> 2, t3 = lane & 3;
    const int q0 = blockIdx.x * 64;
    const int bh = blockIdx.y;
    const int b  = bh / HH, h = bh % HH;

    const uint32_t Qb  = smem_u32(&Qs[0][0]);
    const uint32_t Kb  = smem_u32(&Ks[0][0][0]);
    const uint32_t Vb  = smem_u32(&Vs[0][0][0]);
    const uint32_t Pb  = smem_u32(&Ps[0][0]);
    const uint32_t BsB = smem_u32(&Bs[0][0][0]);

    const int arow = lane & 15;
    const int acol = (lane >> 4) * 16;
    const int brow = (lane & 7) + ((lane >> 4) & 1) * 8;
    const int bcol = ((lane >> 3) & 1) * 16;
    const int vrow = (lane & 7) + ((lane >> 3) & 1) * 8;
    const int vcol = (lane >> 4) * 16;

    auto prefetch = [&](int kc) {
        const int b3 = kc % 3;
        const int b4 = kc & 3;
        const int k0 = kc * 32;
#pragma unroll
        for (int i = 0; i < 2; i++) {
            const int idx = t + 128 * i;
            const int row = idx >> 3, seg = idx & 7;
            const size_t base = (size_t)(b * LL + k0 + row) * QKVN + h * 64 + seg * 8;
            cp16(Kb + (uint32_t)(b3 * 4608 + row * 144 + seg * 16), g_qkvh + base + 768);
            cp16(Vb + (uint32_t)(b4 * 4608 + row * 144 + seg * 16), g_qkvh + base + 1536);
        }
#pragma unroll
        for (int i = 0; i < 4; i++) {
            const int idx = t + 128 * i;
            const int row = idx >> 3, seg = idx & 7;
            cp16(BsB + (uint32_t)(b3 * 9216 + row * 144 + seg * 16),
                 bias + ((size_t)bh * 1024 + q0 + row) * 1024 + k0 + seg * 4);
        }
        cp_commit();
    };

    // Q tile folded into prefetch(0)'s commit group
#pragma unroll
    for (int i = 0; i < 4; i++) {
        const int idx = t + 128 * i;
        const int row = idx >> 3, seg = idx & 7;
        cp16(Qb + (uint32_t)(row * 144 + seg * 16),
             g_qkvh + (size_t)(b * LL + q0 + row) * QKVN + h * 64 + seg * 8);
    }
    prefetch(0);
    prefetch(1);

    float o[8][4];
#pragma unroll
    for (int nf = 0; nf < 8; nf++)
#pragma unroll
        for (int r = 0; r < 4; r++) o[nf][r] = 0.f;
    float psum0 = 0.f, psum1 = 0.f;

    const int ql = w * 16 + g;

    auto S_phase = [&](int kc, float s[4][4]) {
        const int b3 = kc % 3;
#pragma unroll
        for (int nf = 0; nf < 4; nf++)
#pragma unroll
            for (int r = 0; r < 4; r++) s[nf][r] = 0.f;
#pragma unroll
        for (int ks = 0; ks < 4; ks++) {
            uint32_t a[4];
            ldm_x4(a, Qb + (uint32_t)((w * 16 + arow) * 144 + acol + ks * 32));
#pragma unroll
            for (int nf2 = 0; nf2 < 2; nf2++) {
                uint32_t bk[4];
                ldm_x4(bk, Kb + (uint32_t)(b3 * 4608 +
                       (nf2 * 16 + brow) * 144 + bcol + ks * 32));
                mma_f16(s[nf2 * 2],     a, &bk[0]);
                mma_f16(s[nf2 * 2 + 1], a, &bk[2]);
            }
        }
    };
    auto PV_phase = [&](int kc) {
        const int b4 = kc & 3;
#pragma unroll
        for (int ks = 0; ks < 2; ks++) {
            uint32_t a[4];
            ldm_x4(a, Pb + (uint32_t)((w * 16 + arow) * 80 + acol + ks * 32));
#pragma unroll
            for (int nf2 = 0; nf2 < 4; nf2++) {
                uint32_t bv[4];
                ldm_x4t(bv, Vb + (uint32_t)(b4 * 4608 +
                        (ks * 16 + vrow) * 144 + vcol + nf2 * 32));
                mma_f16(o[nf2 * 2],     a, &bv[0]);
                mma_f16(o[nf2 * 2 + 1], a, &bv[2]);
            }
        }
    };
    auto EXP_phase = [&](int kc, float s[4][4]) {
        const int b3 = kc % 3;
#pragma unroll
        for (int nf = 0; nf < 4; nf++) {
            const int kvl = nf * 8 + 2 * t3;
            const float2 bv0 = *(const float2*)&Bs[b3][ql][kvl];
            const float2 bv1 = *(const float2*)&Bs[b3][ql + 8][kvl];
            const float e0 = __expf(s[nf][0] * 0.125f + bv0.x);
            const float e1 = __expf(s[nf][1] * 0.125f + bv0.y);
            const float e2 = __expf(s[nf][2] * 0.125f + bv1.x);
            const float e3 = __expf(s[nf][3] * 0.125f + bv1.y);
            psum0 += e0 + e1;
            psum1 += e2 + e3;
            *(__half2*)&Ps[ql][kvl]     = __floats2half2_rn(e0, e1);
            *(__half2*)&Ps[ql + 8][kvl] = __floats2half2_rn(e2, e3);
        }
        __syncwarp();
    };

    {   // iteration 0 (peeled)
        float s[4][4];
        cp_wait1();
        __syncthreads();
        prefetch(2);
        S_phase(0, s);
        EXP_phase(0, s);
    }
    for (int kc = 1; kc < 16; kc++) {
        float s[4][4];
        if (kc < 15) cp_wait1(); else cp_wait0();
        __syncthreads();
        if (kc + 2 < 16) prefetch(kc + 2);
        S_phase(kc, s);
        PV_phase(kc - 1);
        EXP_phase(kc, s);
    }
    PV_phase(15);

    psum0 += __shfl_xor_sync(0xffffffffu, psum0, 1);
    psum0 += __shfl_xor_sync(0xffffffffu, psum0, 2);
    psum1 += __shfl_xor_sync(0xffffffffu, psum1, 1);
    psum1 += __shfl_xor_sync(0xffffffffu, psum1, 2);
    if (t3 == 0) {
        rs[ql]     = psum0;
        rs[ql + 8] = psum1;
    }
    __syncthreads();

    const float inv0 = 1.f / rs[ql];
    const float inv1 = 1.f / rs[ql + 8];
    const size_t row0 = (size_t)(b * LL + q0 + ql) * 768 + h * 64;
#pragma unroll
    for (int nf = 0; nf < 8; nf++) {
        const int col = nf * 8 + 2 * t3;
        *(float2*)&out[row0 + col] =
            make_float2(o[nf][0] * inv0, o[nf][1] * inv0);
        *(float2*)&out[row0 + (size_t)8 * 768 + col] =
            make_float2(o[nf][2] * inv1, o[nf][3] * inv1);
    }
}

// ---------------------------------------------------------------------------
extern "C" void kernel_launch(void* const* d_in, const int* in_sizes, int n_in,
                              void* d_out, int out_size) {
    const float* X    = (const float*)d_in[0];   // hidden_states [2048,768]
    const float* W    = (const float*)d_in[1];   // Wqkv_w [2304,768]
    const float* Wb   = (const float*)d_in[2];   // Wqkv_b [2304]
    const float* bias = (const float*)d_in[3];   // bias [4,12,1024,1024]
    float* out = (float*)d_out;                  // [2048,768] fp32

    qkv_h<<<dim3(18, 16), 256>>>(X, W, Wb);
    attn_h<<<dim3(8, BHH), 128>>>(bias, out);
}

// round 10
// speedup vs baseline: 1.3643x; 1.3643x over previous
#include <cuda_runtime.h>
#include <cuda_fp16.h>
#include <cstdint>

// Problem constants (fixed by the dataset's setup_inputs)
#define HH   12
#define LL   512
#define QKVN 2304       // 3*768
#define NNZZ 2048       // B*L
#define BHH  48         // B*H

// Scratch (allocation-free rule: __device__ globals)
__device__ __half g_qkvh[(size_t)NNZZ * QKVN];   // QKV output, fp16
__device__ __half g_xh[(size_t)NNZZ * 768];      // X in fp16
__device__ __half g_wh[(size_t)QKVN * 768];      // W in fp16

// ---------------------------------------------------------------------------
// helpers
// ---------------------------------------------------------------------------
__device__ __forceinline__ uint32_t smem_u32(const void* p) {
    uint32_t a;
    asm("{ .reg .u64 t; cvta.to.shared.u64 t, %1; cvt.u32.u64 %0, t; }"
        : "=r"(a) : "l"(p));
    return a;
}
__device__ __forceinline__ void mma_f16(float* c, const uint32_t* a, const uint32_t* b) {
    asm volatile(
        "mma.sync.aligned.m16n8k16.row.col.f32.f16.f16.f32 "
        "{%0,%1,%2,%3},{%4,%5,%6,%7},{%8,%9},{%0,%1,%2,%3};"
        : "+f"(c[0]), "+f"(c[1]), "+f"(c[2]), "+f"(c[3])
        : "r"(a[0]), "r"(a[1]), "r"(a[2]), "r"(a[3]), "r"(b[0]), "r"(b[1]));
}
__device__ __forceinline__ void ldm_x4(uint32_t* r, uint32_t addr) {
    asm volatile("ldmatrix.sync.aligned.m8n8.x4.shared.b16 {%0,%1,%2,%3}, [%4];"
                 : "=r"(r[0]), "=r"(r[1]), "=r"(r[2]), "=r"(r[3]) : "r"(addr));
}
__device__ __forceinline__ void ldm_x4t(uint32_t* r, uint32_t addr) {
    asm volatile("ldmatrix.sync.aligned.m8n8.x4.trans.shared.b16 {%0,%1,%2,%3}, [%4];"
                 : "=r"(r[0]), "=r"(r[1]), "=r"(r[2]), "=r"(r[3]) : "r"(addr));
}
__device__ __forceinline__ void cp16(uint32_t dst, const void* src) {
    asm volatile("cp.async.cg.shared.global [%0], [%1], 16;" :: "r"(dst), "l"(src));
}
__device__ __forceinline__ void cp_commit() { asm volatile("cp.async.commit_group;"); }
__device__ __forceinline__ void cp_wait1()  { asm volatile("cp.async.wait_group 1;"); }
__device__ __forceinline__ void cp_wait0()  { asm volatile("cp.async.wait_group 0;"); }

// ---------------------------------------------------------------------------
// Kernel 0: fp32 -> fp16, branch-free exact tiling.
// 408 blocks x 2048 float4; blocks [0,192) cover X, [192,408) cover W.
// 8 independent LDG.128 per thread (MLP=8), then 8 STG.64.
// ---------------------------------------------------------------------------
__global__ void __launch_bounds__(256) cvt_f2h(const float* __restrict__ X,
                                               const float* __restrict__ W) {
    const int bi = blockIdx.x;
    const float* src;
    __half* dst;
    int base;
    if (bi < 192) { src = X; dst = g_xh; base = bi * 2048; }
    else          { src = W; dst = g_wh; base = (bi - 192) * 2048; }
    const int tid = threadIdx.x;

    float4 v[8];
#pragma unroll
    for (int u = 0; u < 8; u++)
        v[u] = ((const float4*)src)[base + u * 256 + tid];
#pragma unroll
    for (int u = 0; u < 8; u++) {
        const int j = base + u * 256 + tid;
        __half2 h0 = __floats2half2_rn(v[u].x, v[u].y);
        __half2 h1 = __floats2half2_rn(v[u].z, v[u].w);
        uint2 uu;
        uu.x = *reinterpret_cast<uint32_t*>(&h0);
        uu.y = *reinterpret_cast<uint32_t*>(&h1);
        *reinterpret_cast<uint2*>(dst + 4 * (size_t)j) = uu;
    }
}

// ---------------------------------------------------------------------------
// Kernel A: QKV = X @ W^T + b  (fp16 mma m16n8k16, 3-stage cp.async)
// Block 128(M) x 128(N), 8 warps, warp 64x32, ktile=32. At the mma.sync floor.
// ---------------------------------------------------------------------------
__global__ void __launch_bounds__(256, 2) qkv_h(const float* __restrict__ Wb) {
    __shared__ __align__(16) __half sA[3][128 * 40];
    __shared__ __align__(16) __half sB[3][128 * 40];
    __shared__ float sWb[128];

    const int t    = threadIdx.x;
    const int w    = t >> 5, lane = t & 31;
    const int g    = lane >> 2, t3 = lane & 3;
    const int wm   = (w >> 2) * 64;
    const int wn   = (w & 3) * 32;
    const int m0   = blockIdx.y * 128;
    const int n0   = blockIdx.x * 128;

    if (t < 128) sWb[t] = Wb[n0 + t];

    float c[4][4][4];
#pragma unroll
    for (int mf = 0; mf < 4; mf++)
#pragma unroll
        for (int nf = 0; nf < 4; nf++)
#pragma unroll
            for (int r = 0; r < 4; r++) c[mf][nf][r] = 0.f;

    const uint32_t aB = smem_u32(&sA[0][0]);
    const uint32_t bB = smem_u32(&sB[0][0]);

    const int arow = lane & 15;
    const int acol = (lane >> 4) * 16;
    const int brow = (lane & 7) + ((lane >> 4) & 1) * 8;
    const int bcol = ((lane >> 3) & 1) * 16;

    auto load_stage = [&](int st, int kt) {
        const int k0 = kt * 32;
#pragma unroll
        for (int i = 0; i < 2; i++) {
            const int idx = t + 256 * i;
            const int row = idx >> 2, seg = idx & 3;
            cp16(aB + (uint32_t)(st * 10240 + row * 80 + seg * 16),
                 g_xh + (size_t)(m0 + row) * 768 + k0 + seg * 8);
            cp16(bB + (uint32_t)(st * 10240 + row * 80 + seg * 16),
                 g_wh + (size_t)(n0 + row) * 768 + k0 + seg * 8);
        }
        cp_commit();
    };

    load_stage(0, 0);
    load_stage(1, 1);
    for (int kt = 0; kt < 24; kt++) {
        const int st = kt % 3;
        if (kt < 23) cp_wait1(); else cp_wait0();
        __syncthreads();
        if (kt + 2 < 24) load_stage((kt + 2) % 3, kt + 2);

#pragma unroll
        for (int ks = 0; ks < 2; ks++) {
            uint32_t a[4][4], bk[2][4];
#pragma unroll
            for (int mf = 0; mf < 4; mf++)
                ldm_x4(a[mf], aB + (uint32_t)(st * 10240 +
                       (wm + mf * 16 + arow) * 80 + acol + ks * 32));
#pragma unroll
            for (int nf2 = 0; nf2 < 2; nf2++)
                ldm_x4(bk[nf2], bB + (uint32_t)(st * 10240 +
                       (wn + nf2 * 16 + brow) * 80 + bcol + ks * 32));
#pragma unroll
            for (int mf = 0; mf < 4; mf++)
#pragma unroll
                for (int nf = 0; nf < 4; nf++) {
                    uint32_t bb[2] = { bk[nf >> 1][(nf & 1) * 2],
                                       bk[nf >> 1][(nf & 1) * 2 + 1] };
                    mma_f16(c[mf][nf], a[mf], bb);
                }
        }
    }

#pragma unroll
    for (int mf = 0; mf < 4; mf++) {
        const int r0 = m0 + wm + mf * 16 + g;
#pragma unroll
        for (int nf = 0; nf < 4; nf++) {
            const int col = n0 + wn + nf * 8 + 2 * t3;
            const float b0 = sWb[col - n0], b1 = sWb[col - n0 + 1];
            __half2 h0 = __floats2half2_rn(c[mf][nf][0] + b0, c[mf][nf][1] + b1);
            __half2 h1 = __floats2half2_rn(c[mf][nf][2] + b0, c[mf][nf][3] + b1);
            *(__half2*)&g_qkvh[(size_t)r0 * QKVN + col]       = h0;
            *(__half2*)&g_qkvh[(size_t)(r0 + 8) * QKVN + col] = h1;
        }
    }
}

// ---------------------------------------------------------------------------
// Kernel B: fused attention, fp16 mma, fp32 accum, one-pass softmax.
// 16 kv-chunks of 32; K/V/bias 2-stage rings with depth-1 cp.async prefetch
// (in-flight time = one chunk's compute >> DRAM latency).
// smem ~52KB, __launch_bounds__(128,4) -> 4 CTAs/SM = 16 warps/SM.
// ---------------------------------------------------------------------------
__global__ void __launch_bounds__(128, 4) attn_h(const float* __restrict__ bias,
                                                 float* __restrict__ out) {
    __shared__ __align__(16) __half Qs[64][72];
    __shared__ __align__(16) __half Ks[2][32][72];
    __shared__ __align__(16) __half Vs[2][32][72];
    __shared__ __align__(16) __half Ps[64][40];
    __shared__ __align__(16) float  Bs[2][64][36];
    __shared__ float rs[64];

    const int t  = threadIdx.x;
    const int w  = t >> 5, lane = t & 31;
    const int g  = lane >> 2, t3 = lane & 3;
    const int q0 = blockIdx.x * 64;
    const int bh = blockIdx.y;
    const int b  = bh / HH, h = bh % HH;

    const uint32_t Qb  = smem_u32(&Qs[0][0]);
    const uint32_t Kb  = smem_u32(&Ks[0][0][0]);
    const uint32_t Vb  = smem_u32(&Vs[0][0][0]);
    const uint32_t Pb  = smem_u32(&Ps[0][0]);
    const uint32_t BsB = smem_u32(&Bs[0][0][0]);

    const int arow = lane & 15;
    const int acol = (lane >> 4) * 16;
    const int brow = (lane & 7) + ((lane >> 4) & 1) * 8;
    const int bcol = ((lane >> 3) & 1) * 16;
    const int vrow = (lane & 7) + ((lane >> 3) & 1) * 8;
    const int vcol = (lane >> 4) * 16;

    auto prefetch = [&](int kc) {
        const int buf = kc & 1;
        const int k0  = kc * 32;
#pragma unroll
        for (int i = 0; i < 2; i++) {            // K + V
            const int idx = t + 128 * i;
            const int row = idx >> 3, seg = idx & 7;
            const size_t base = (size_t)(b * LL + k0 + row) * QKVN + h * 64 + seg * 8;
            cp16(Kb + (uint32_t)(buf * 4608 + row * 144 + seg * 16), g_qkvh + base + 768);
            cp16(Vb + (uint32_t)(buf * 4608 + row * 144 + seg * 16), g_qkvh + base + 1536);
        }
#pragma unroll
        for (int i = 0; i < 4; i++) {            // bias: 64 rows x 128B
            const int idx = t + 128 * i;
            const int row = idx >> 3, seg = idx & 7;
            cp16(BsB + (uint32_t)(buf * 9216 + row * 144 + seg * 16),
                 bias + ((size_t)bh * 1024 + q0 + row) * 1024 + k0 + seg * 4);
        }
        cp_commit();
    };

    // Q tile folded into prefetch(0)'s commit group
#pragma unroll
    for (int i = 0; i < 4; i++) {
        const int idx = t + 128 * i;
        const int row = idx >> 3, seg = idx & 7;
        cp16(Qb + (uint32_t)(row * 144 + seg * 16),
             g_qkvh + (size_t)(b * LL + q0 + row) * QKVN + h * 64 + seg * 8);
    }
    prefetch(0);

    float o[8][4];
#pragma unroll
    for (int nf = 0; nf < 8; nf++)
#pragma unroll
        for (int r = 0; r < 4; r++) o[nf][r] = 0.f;
    float psum0 = 0.f, psum1 = 0.f;

    const int ql = w * 16 + g;

    for (int kc = 0; kc < 16; kc++) {
        const int buf = kc & 1;
        cp_wait0();
        __syncthreads();                 // chunk kc visible; prev reads done
        if (kc + 1 < 16) prefetch(kc + 1);   // fills the other buffer

        // S = Q K^T   (warp: 16 q x 32 kv)
        float s[4][4];
#pragma unroll
        for (int nf = 0; nf < 4; nf++)
#pragma unroll
            for (int r = 0; r < 4; r++) s[nf][r] = 0.f;
#pragma unroll
        for (int ks = 0; ks < 4; ks++) {
            uint32_t a[4];
            ldm_x4(a, Qb + (uint32_t)((w * 16 + arow) * 144 + acol + ks * 32));
#pragma unroll
            for (int nf2 = 0; nf2 < 2; nf2++) {
                uint32_t bk[4];
                ldm_x4(bk, Kb + (uint32_t)(buf * 4608 +
                       (nf2 * 16 + brow) * 144 + bcol + ks * 32));
                mma_f16(s[nf2 * 2],     a, &bk[0]);
                mma_f16(s[nf2 * 2 + 1], a, &bk[2]);
            }
        }

        // bias + exp + P (fp16) + rowsum
#pragma unroll
        for (int nf = 0; nf < 4; nf++) {
            const int kvl = nf * 8 + 2 * t3;
            const float2 bv0 = *(const float2*)&Bs[buf][ql][kvl];
            const float2 bv1 = *(const float2*)&Bs[buf][ql + 8][kvl];
            const float e0 = __expf(s[nf][0] * 0.125f + bv0.x);
            const float e1 = __expf(s[nf][1] * 0.125f + bv0.y);
            const float e2 = __expf(s[nf][2] * 0.125f + bv1.x);
            const float e3 = __expf(s[nf][3] * 0.125f + bv1.y);
            psum0 += e0 + e1;
            psum1 += e2 + e3;
            *(__half2*)&Ps[ql][kvl]     = __floats2half2_rn(e0, e1);
            *(__half2*)&Ps[ql + 8][kvl] = __floats2half2_rn(e2, e3);
        }
        __syncwarp();   // P rows private to this warp

        // O += P V   (warp: its 16 q rows x 64 d), V via ldmatrix.trans
#pragma unroll
        for (int ks = 0; ks < 2; ks++) {
            uint32_t a[4];
            ldm_x4(a, Pb + (uint32_t)((w * 16 + arow) * 80 + acol + ks * 32));
#pragma unroll
            for (int nf2 = 0; nf2 < 4; nf2++) {
                uint32_t bv[4];
                ldm_x4t(bv, Vb + (uint32_t)(buf * 4608 +
                        (ks * 16 + vrow) * 144 + vcol + nf2 * 32));
                mma_f16(o[nf2 * 2],     a, &bv[0]);
                mma_f16(o[nf2 * 2 + 1], a, &bv[2]);
            }
        }
    }

    // rowsum reduce across the quad (lanes sharing g)
    psum0 += __shfl_xor_sync(0xffffffffu, psum0, 1);
    psum0 += __shfl_xor_sync(0xffffffffu, psum0, 2);
    psum1 += __shfl_xor_sync(0xffffffffu, psum1, 1);
    psum1 += __shfl_xor_sync(0xffffffffu, psum1, 2);
    if (t3 == 0) {
        rs[ql]     = psum0;
        rs[ql + 8] = psum1;
    }
    __syncthreads();

    // epilogue: out[q][d] = O(q,d) / rowsum[q]
    const float inv0 = 1.f / rs[ql];
    const float inv1 = 1.f / rs[ql + 8];
    const size_t row0 = (size_t)(b * LL + q0 + ql) * 768 + h * 64;
#pragma unroll
    for (int nf = 0; nf < 8; nf++) {
        const int col = nf * 8 + 2 * t3;
        *(float2*)&out[row0 + col] =
            make_float2(o[nf][0] * inv0, o[nf][1] * inv0);
        *(float2*)&out[row0 + (size_t)8 * 768 + col] =
            make_float2(o[nf][2] * inv1, o[nf][3] * inv1);
    }
}

// ---------------------------------------------------------------------------
extern "C" void kernel_launch(void* const* d_in, const int* in_sizes, int n_in,
                              void* d_out, int out_size) {
    const float* X    = (const float*)d_in[0];   // hidden_states [2048,768]
    const float* W    = (const float*)d_in[1];   // Wqkv_w [2304,768]
    const float* Wb   = (const float*)d_in[2];   // Wqkv_b [2304]
    const float* bias = (const float*)d_in[3];   // bias [4,12,1024,1024]
    float* out = (float*)d_out;                  // [2048,768] fp32

    cvt_f2h<<<408, 256>>>(X, W);
    qkv_h<<<dim3(18, 16), 256>>>(Wb);
    attn_h<<<dim3(8, BHH), 128>>>(bias, out);
}